// round 1
// baseline (speedup 1.0000x reference)
#include <cuda_runtime.h>
#include <math.h>

#define N_MAX 50000
#define F 128
#define H 128

typedef unsigned long long ull;

// Scratch (device globals; no allocation allowed)
__device__ float g_HA[N_MAX * H];   // h @ We1[0:128]   + be1
__device__ float g_HB[N_MAX * H];   // h @ We1[128:256]
__device__ float g_num[N_MAX * H];  // segment sum of edge messages
__device__ float g_deg[N_MAX];      // segment counts

__device__ __forceinline__ float silu_f(float v) {
    return __fdividef(v, 1.0f + __expf(-v));
}
__device__ __forceinline__ ull pk2(float x) {
    ull r; asm("mov.b64 %0, {%1, %1};" : "=l"(r) : "f"(x)); return r;
}
__device__ __forceinline__ ull pkxy(float x, float y) {
    ull r; asm("mov.b64 %0, {%1, %2};" : "=l"(r) : "f"(x), "f"(y)); return r;
}
__device__ __forceinline__ void upk(ull v, float& x, float& y) {
    asm("mov.b64 {%0, %1}, %2;" : "=f"(x), "=f"(y) : "l"(v));
}
__device__ __forceinline__ void ffma2(ull& d, ull a, ull b) {
    asm("fma.rn.f32x2 %0, %1, %2, %0;" : "+l"(d) : "l"(a), "l"(b));
}

// C(128x128) += A(128xK, row-major lda) * B(Kx128, row-major 128)
// 256 threads as 16x16; each thread owns an 8(row) x 8(col) tile, cols packed
// in f32x2 pairs. A values broadcast via pk2; B pairs are natural memory pairs.
__device__ __forceinline__ void gemm_tile(const float* As, int lda, const float* Bs,
                                          int K, int ty8, int tx8, ull acc[8][4]) {
#pragma unroll 4
    for (int k = 0; k < K; k++) {
        const float4 b0 = *(const float4*)(Bs + k * 128 + tx8);
        const float4 b1 = *(const float4*)(Bs + k * 128 + tx8 + 4);
        ull bp0 = pkxy(b0.x, b0.y), bp1 = pkxy(b0.z, b0.w);
        ull bp2 = pkxy(b1.x, b1.y), bp3 = pkxy(b1.z, b1.w);
#pragma unroll
        for (int e = 0; e < 8; e++) {
            ull ap = pk2(As[(ty8 + e) * lda + k]);
            ffma2(acc[e][0], ap, bp0);
            ffma2(acc[e][1], ap, bp1);
            ffma2(acc[e][2], ap, bp2);
            ffma2(acc[e][3], ap, bp3);
        }
    }
}

// ---------------------------------------------------------------- zero
__global__ void k_zero(int n) {
    int total = n * H + n;
    for (int i = blockIdx.x * blockDim.x + threadIdx.x; i < total;
         i += gridDim.x * blockDim.x) {
        if (i < n * H) g_num[i] = 0.0f;
        else           g_deg[i - n * H] = 0.0f;
    }
}

// ---------------------------------------------------------------- degree
__global__ void k_deg(const int* __restrict__ ei, int E) {
    int i = blockIdx.x * blockDim.x + threadIdx.x;
    if (i < E) atomicAdd(&g_deg[ei[i]], 1.0f);
}

// ---------------------------------------------------------------- precompute HA/HB
// grid (ceil(n/128), 2): y=0 -> HA (+be1), y=1 -> HB
#define SM_PRE ((128 * 132 + 128 * 128) * 4)
__global__ void __launch_bounds__(256, 1)
k_pre(const float* __restrict__ h, const float* __restrict__ We1,
      const float* __restrict__ be1, int n) {
    extern __shared__ float sm[];
    float* ht = sm;              // [128][132]
    float* Ws = sm + 128 * 132;  // [128][128]
    int tid = threadIdx.x;
    int n0 = blockIdx.x * 128;
    int part = blockIdx.y;
    const float* W = We1 + (size_t)part * 128 * H;
    float* dst = (part == 0) ? g_HA : g_HB;

    for (int i = tid; i < 128 * 32; i += 256) {
        int nn = i >> 5, jv = i & 31;
        float4 v = make_float4(0.f, 0.f, 0.f, 0.f);
        if (n0 + nn < n) v = *(const float4*)(h + (size_t)(n0 + nn) * F + jv * 4);
        *(float4*)(ht + nn * 132 + jv * 4) = v;
    }
    for (int i = tid; i < 128 * 32; i += 256)
        *(float4*)(Ws + i * 4) = *(const float4*)(W + i * 4);
    __syncthreads();

    int tx = tid & 15, ty = tid >> 4;
    int tx8 = tx * 8, ty8 = ty * 8;
    ull acc[8][4];
#pragma unroll
    for (int e = 0; e < 8; e++)
#pragma unroll
        for (int j = 0; j < 4; j++) acc[e][j] = 0ull;

    gemm_tile(ht, 132, Ws, 128, ty8, tx8, acc);

#pragma unroll
    for (int e = 0; e < 8; e++) {
        int nn = ty8 + e;
        if (n0 + nn >= n) continue;
        float o[8];
#pragma unroll
        for (int jp = 0; jp < 4; jp++) upk(acc[e][jp], o[2 * jp], o[2 * jp + 1]);
        if (part == 0) {
#pragma unroll
            for (int j = 0; j < 8; j++) o[j] += __ldg(be1 + tx8 + j);
        }
        float* p = dst + (size_t)(n0 + nn) * H + tx8;
        *(float4*)p       = make_float4(o[0], o[1], o[2], o[3]);
        *(float4*)(p + 4) = make_float4(o[4], o[5], o[6], o[7]);
    }
}

// ---------------------------------------------------------------- edge kernel
// one CTA = 128 edges: dist -> m1 = silu(HA[row]+HB[col]+dist*wr) -> m1@We2
// -> silu -> atomic scatter into g_num[row]
#define SM_EDGE ((128 * 128 + 128 * 132 + 128) * 4 + 128 * 2 * 4)
__global__ void __launch_bounds__(256, 1)
k_edge(const float* __restrict__ xz, const int* __restrict__ ei,
       const float* __restrict__ We1, const float* __restrict__ We2,
       const float* __restrict__ be2, int E) {
    extern __shared__ float sm[];
    float* W2s   = sm;                       // [128][128]
    float* m1    = sm + 128 * 128;           // [128][132] (edge-major)
    float* distS = m1 + 128 * 132;           // [128]
    int*   rowS  = (int*)(distS + 128);      // [128]
    int*   colS  = rowS + 128;               // [128]
    int tid = threadIdx.x;
    int e0 = blockIdx.x * 128;
    const int* rowp = ei;
    const int* colp = ei + E;

    for (int i = tid; i < 128 * 32; i += 256)
        *(float4*)(W2s + i * 4) = *(const float4*)(We2 + i * 4);

    if (tid < 128) {
        int g = e0 + tid;
        if (g < E) {
            int r = rowp[g], c = colp[g];
            float rx = xz[3 * r], ry = xz[3 * r + 1], rz = xz[3 * r + 2];
            float cx = xz[3 * c], cy = xz[3 * c + 1], cz = xz[3 * c + 2];
            float dx = rx - cx, dy = ry - cy, dz = rz - cz;
            float u = (dx * dx + dy * dy + dz * dz) / (2.0f * rz * cz);
            distS[tid] = acoshf(1.0f + u);
            rowS[tid] = r;
            colS[tid] = c;
        } else {
            rowS[tid] = -1; colS[tid] = 0; distS[tid] = 0.0f;
        }
    }
    __syncthreads();

    // phase A: m1 tile (coalesced 512B row gathers; e constant per warp)
    const float* wr = We1 + 256 * H;  // radial weight row of We1
    for (int i = tid; i < 128 * 32; i += 256) {
        int e = i >> 5, jv = i & 31;
        int r = rowS[e];
        float4 v = make_float4(0.f, 0.f, 0.f, 0.f);
        if (r >= 0) {
            int c = colS[e];
            float4 ha = *(const float4*)(g_HA + (size_t)r * H + jv * 4);
            float4 hb = *(const float4*)(g_HB + (size_t)c * H + jv * 4);
            float4 w  = __ldg((const float4*)(wr + jv * 4));
            float d = distS[e];
            v.x = silu_f(ha.x + hb.x + d * w.x);
            v.y = silu_f(ha.y + hb.y + d * w.y);
            v.z = silu_f(ha.z + hb.z + d * w.z);
            v.w = silu_f(ha.w + hb.w + d * w.w);
        }
        *(float4*)(m1 + e * 132 + jv * 4) = v;
    }
    __syncthreads();

    int tx = tid & 15, ty = tid >> 4;
    int tx8 = tx * 8, ty8 = ty * 8;
    ull acc[8][4];
#pragma unroll
    for (int e = 0; e < 8; e++)
#pragma unroll
        for (int j = 0; j < 4; j++) acc[e][j] = 0ull;

    gemm_tile(m1, 132, W2s, 128, ty8, tx8, acc);

    float b2[8];
#pragma unroll
    for (int j = 0; j < 8; j++) b2[j] = __ldg(be2 + tx8 + j);

#pragma unroll
    for (int e = 0; e < 8; e++) {
        int r = rowS[ty8 + e];
        if (r < 0) continue;
        float* dstp = g_num + (size_t)r * H + tx8;
#pragma unroll
        for (int jp = 0; jp < 4; jp++) {
            float x, y;
            upk(acc[e][jp], x, y);
            atomicAdd(dstp + 2 * jp,     silu_f(x + b2[2 * jp]));
            atomicAdd(dstp + 2 * jp + 1, silu_f(y + b2[2 * jp + 1]));
        }
    }
}

// ---------------------------------------------------------------- node kernel
// out = h + silu([h | num/max(deg,1)] @ Wn1 + bn1) @ Wn2 + bn2
#define SM_NODE ((128 * 36 + 32 * 128 + 128 * 128 + 128 * 132 + 128) * 4)
__global__ void __launch_bounds__(256, 1)
k_node(const float* __restrict__ h, const float* __restrict__ Wn1,
       const float* __restrict__ bn1, const float* __restrict__ Wn2,
       const float* __restrict__ bn2, float* __restrict__ out, int n) {
    extern __shared__ float sm[];
    float* zt  = sm;                                   // [128][36] chunk of z (32 k + pad)
    float* Ws  = zt + 128 * 36;                        // [32][128] Wn1 chunk
    float* W2s = Ws + 32 * 128;                        // [128][128] Wn2
    float* t1  = W2s + 128 * 128;                      // [128][132] stage-1 act
    float* idg = t1 + 128 * 132;                       // [128] 1/max(deg,1)
    int tid = threadIdx.x;
    int n0 = blockIdx.x * 128;

    for (int i = tid; i < 128 * 32; i += 256)
        *(float4*)(W2s + i * 4) = *(const float4*)(Wn2 + i * 4);
    if (tid < 128) {
        float d = (n0 + tid < n) ? g_deg[n0 + tid] : 1.0f;
        idg[tid] = 1.0f / fmaxf(d, 1.0f);
    }
    __syncthreads();

    int tx = tid & 15, ty = tid >> 4;
    int tx8 = tx * 8, ty8 = ty * 8;
    ull acc[8][4];
#pragma unroll
    for (int e = 0; e < 8; e++)
#pragma unroll
        for (int j = 0; j < 4; j++) acc[e][j] = 0ull;

    // stage 1: K = 256 in 8 chunks of 32
    for (int kc = 0; kc < 8; kc++) {
        for (int i = tid; i < 128 * 8; i += 256) {
            int nn = i >> 3, jv = i & 7;
            int nz = n0 + nn;
            float4 v = make_float4(0.f, 0.f, 0.f, 0.f);
            if (nz < n) {
                if (kc < 4) {
                    v = *(const float4*)(h + (size_t)nz * F + kc * 32 + jv * 4);
                } else {
                    v = *(const float4*)(g_num + (size_t)nz * H + (kc - 4) * 32 + jv * 4);
                    float s = idg[nn];
                    v.x *= s; v.y *= s; v.z *= s; v.w *= s;
                }
            }
            *(float4*)(zt + nn * 36 + jv * 4) = v;
        }
        for (int i = tid; i < 32 * 32; i += 256)
            *(float4*)(Ws + i * 4) =
                *(const float4*)(Wn1 + (size_t)kc * 32 * H + i * 4);
        __syncthreads();
        gemm_tile(zt, 36, Ws, 32, ty8, tx8, acc);
        __syncthreads();
    }

    // t1 = silu(acc + bn1)
#pragma unroll
    for (int e = 0; e < 8; e++) {
        int nn = ty8 + e;
        float o[8];
#pragma unroll
        for (int jp = 0; jp < 4; jp++) upk(acc[e][jp], o[2 * jp], o[2 * jp + 1]);
#pragma unroll
        for (int j = 0; j < 8; j++)
            t1[nn * 132 + tx8 + j] = silu_f(o[j] + __ldg(bn1 + tx8 + j));
    }
    __syncthreads();

    // stage 2: t1 @ Wn2 + residual
    ull acc2[8][4];
#pragma unroll
    for (int e = 0; e < 8; e++)
#pragma unroll
        for (int j = 0; j < 4; j++) acc2[e][j] = 0ull;

    gemm_tile(t1, 132, W2s, 128, ty8, tx8, acc2);

#pragma unroll
    for (int e = 0; e < 8; e++) {
        int nn = ty8 + e;
        if (n0 + nn >= n) continue;
        const float* hp = h + (size_t)(n0 + nn) * F + tx8;
        float4 h0 = *(const float4*)hp;
        float4 h1 = *(const float4*)(hp + 4);
        float o[8];
#pragma unroll
        for (int jp = 0; jp < 4; jp++) upk(acc2[e][jp], o[2 * jp], o[2 * jp + 1]);
        float4 r0 = make_float4(h0.x + o[0] + __ldg(bn2 + tx8 + 0),
                                h0.y + o[1] + __ldg(bn2 + tx8 + 1),
                                h0.z + o[2] + __ldg(bn2 + tx8 + 2),
                                h0.w + o[3] + __ldg(bn2 + tx8 + 3));
        float4 r1 = make_float4(h1.x + o[4] + __ldg(bn2 + tx8 + 4),
                                h1.y + o[5] + __ldg(bn2 + tx8 + 5),
                                h1.z + o[6] + __ldg(bn2 + tx8 + 6),
                                h1.w + o[7] + __ldg(bn2 + tx8 + 7));
        float* op = out + (size_t)(n0 + nn) * F + tx8;
        *(float4*)op       = r0;
        *(float4*)(op + 4) = r1;
    }
}

// ---------------------------------------------------------------- launch
extern "C" void kernel_launch(void* const* d_in, const int* in_sizes, int n_in,
                              void* d_out, int out_size) {
    const float* xz  = (const float*)d_in[0];
    const float* h   = (const float*)d_in[1];
    const float* We1 = (const float*)d_in[2];
    const float* be1 = (const float*)d_in[3];
    const float* We2 = (const float*)d_in[4];
    const float* be2 = (const float*)d_in[5];
    const float* Wn1 = (const float*)d_in[6];
    const float* bn1 = (const float*)d_in[7];
    const float* Wn2 = (const float*)d_in[8];
    const float* bn2 = (const float*)d_in[9];
    const int*   ei  = (const int*)d_in[10];
    float* out = (float*)d_out;

    int n = in_sizes[1] / F;
    int E = in_sizes[10] / 2;

    cudaFuncSetAttribute(k_pre,  cudaFuncAttributeMaxDynamicSharedMemorySize, SM_PRE);
    cudaFuncSetAttribute(k_edge, cudaFuncAttributeMaxDynamicSharedMemorySize, SM_EDGE);
    cudaFuncSetAttribute(k_node, cudaFuncAttributeMaxDynamicSharedMemorySize, SM_NODE);

    int nb = (n + 127) / 128;
    k_zero<<<2048, 256>>>(n);
    k_pre<<<dim3(nb, 2), 256, SM_PRE>>>(h, We1, be1, n);
    k_deg<<<(E + 255) / 256, 256>>>(ei, E);
    k_edge<<<(E + 127) / 128, 256, SM_EDGE>>>(xz, ei, We1, We2, be2, E);
    k_node<<<nb, 256, SM_NODE>>>(h, Wn1, bn1, Wn2, bn2, out, n);
}

// round 2
// speedup vs baseline: 1.5013x; 1.5013x over previous
#include <cuda_runtime.h>
#include <math.h>

#define N_MAX 50000
#define F 128
#define H 128

typedef unsigned long long ull;

// Scratch (device globals; no allocation allowed)
__device__ float g_HA[N_MAX * H];   // h @ We1[0:128]   + be1
__device__ float g_HB[N_MAX * H];   // h @ We1[128:256]
__device__ float g_num[N_MAX * H];  // segment sum of edge messages
__device__ float g_deg[N_MAX];      // segment counts

__device__ __forceinline__ float silu_f(float v) {
    return __fdividef(v, 1.0f + __expf(-v));
}
__device__ __forceinline__ ull pk2(float x) {
    ull r; asm("mov.b64 %0, {%1, %1};" : "=l"(r) : "f"(x)); return r;
}
__device__ __forceinline__ ull pkxy(float x, float y) {
    ull r; asm("mov.b64 %0, {%1, %2};" : "=l"(r) : "f"(x), "f"(y)); return r;
}
__device__ __forceinline__ void upk(ull v, float& x, float& y) {
    asm("mov.b64 {%0, %1}, %2;" : "=f"(x), "=f"(y) : "l"(v));
}
__device__ __forceinline__ void ffma2(ull& d, ull a, ull b) {
    asm("fma.rn.f32x2 %0, %1, %2, %0;" : "+l"(d) : "l"(a), "l"(b));
}
__device__ __forceinline__ void red_add_v4(float* p, float x, float y, float z, float w) {
    asm volatile("red.global.add.v4.f32 [%0], {%1, %2, %3, %4};"
                 :: "l"(p), "f"(x), "f"(y), "f"(z), "f"(w) : "memory");
}

// C(rows x cols) += A(rows x K, row-major lda) * B(K x cols, row-major ldb)
// each thread owns RPT rows x 8 cols, cols packed in f32x2 pairs.
template <int RPT>
__device__ __forceinline__ void gemm_tile(const float* As, int lda,
                                          const float* Bs, int ldb, int K,
                                          int row0, int tx8, ull acc[][4]) {
#pragma unroll 4
    for (int k = 0; k < K; k++) {
        const float4 b0 = *(const float4*)(Bs + k * ldb + tx8);
        const float4 b1 = *(const float4*)(Bs + k * ldb + tx8 + 4);
        ull bp0 = pkxy(b0.x, b0.y), bp1 = pkxy(b0.z, b0.w);
        ull bp2 = pkxy(b1.x, b1.y), bp3 = pkxy(b1.z, b1.w);
#pragma unroll
        for (int e = 0; e < RPT; e++) {
            ull ap = pk2(As[(row0 + e) * lda + k]);
            ffma2(acc[e][0], ap, bp0);
            ffma2(acc[e][1], ap, bp1);
            ffma2(acc[e][2], ap, bp2);
            ffma2(acc[e][3], ap, bp3);
        }
    }
}

// ---------------------------------------------------------------- zero
__global__ void k_zero(int n) {
    int t4 = n * (H / 4);
    float4 z4 = make_float4(0.f, 0.f, 0.f, 0.f);
    for (int i = blockIdx.x * blockDim.x + threadIdx.x; i < t4 + n;
         i += gridDim.x * blockDim.x) {
        if (i < t4) ((float4*)g_num)[i] = z4;
        else        g_deg[i - t4] = 0.0f;
    }
}

// ---------------------------------------------------------------- degree
__global__ void k_deg(const int* __restrict__ ei, int E) {
    int i = blockIdx.x * blockDim.x + threadIdx.x;
    if (i < E) atomicAdd(&g_deg[ei[i]], 1.0f);
}

// ---------------------------------------------------------------- precompute HA/HB
// Fused: one CTA computes both HA (cols 0..127, +be1) and HB (cols 128..255)
// for 128 nodes; h tile loaded once. 512 threads, thread tile 8x8.
#define SM_PRE ((128 * 132 + 128 * 256) * 4)
__global__ void __launch_bounds__(512, 1)
k_pre(const float* __restrict__ h, const float* __restrict__ We1,
      const float* __restrict__ be1, int n) {
    extern __shared__ float sm[];
    float* ht = sm;              // [128][132]
    float* Ws = sm + 128 * 132;  // [128][256] = [We1 part0 | We1 part1]
    int tid = threadIdx.x;
    int n0 = blockIdx.x * 128;

    for (int i = tid; i < 128 * 32; i += 512) {
        int nn = i >> 5, jv = i & 31;
        float4 v = make_float4(0.f, 0.f, 0.f, 0.f);
        if (n0 + nn < n) v = *(const float4*)(h + (size_t)(n0 + nn) * F + jv * 4);
        *(float4*)(ht + nn * 132 + jv * 4) = v;
    }
    for (int i = tid; i < 128 * 64; i += 512) {  // float4 index over [128][256]
        int k = i >> 6;
        int col = (i & 63) * 4;
        const float* src = (col < 128)
            ? (We1 + (size_t)k * 128 + col)
            : (We1 + (size_t)(128 + k) * 128 + (col - 128));
        *(float4*)(Ws + k * 256 + col) = *(const float4*)src;
    }
    __syncthreads();

    int tx = tid & 31, ty = tid >> 5;
    int tx8 = tx * 8, ty8 = ty * 8;
    ull acc[8][4];
#pragma unroll
    for (int e = 0; e < 8; e++)
#pragma unroll
        for (int j = 0; j < 4; j++) acc[e][j] = 0ull;

    gemm_tile<8>(ht, 132, Ws, 256, 128, ty8, tx8, acc);

    bool isA = (tx8 < 128);
    float* dstb = isA ? g_HA : g_HB;
    int cb = isA ? tx8 : (tx8 - 128);
    float bias[8];
#pragma unroll
    for (int j = 0; j < 8; j++) bias[j] = isA ? __ldg(be1 + cb + j) : 0.0f;

#pragma unroll
    for (int e = 0; e < 8; e++) {
        int nn = ty8 + e;
        if (n0 + nn >= n) continue;
        float o[8];
#pragma unroll
        for (int jp = 0; jp < 4; jp++) upk(acc[e][jp], o[2 * jp], o[2 * jp + 1]);
#pragma unroll
        for (int j = 0; j < 8; j++) o[j] += bias[j];
        float* p = dstb + (size_t)(n0 + nn) * H + cb;
        *(float4*)p       = make_float4(o[0], o[1], o[2], o[3]);
        *(float4*)(p + 4) = make_float4(o[4], o[5], o[6], o[7]);
    }
}

// ---------------------------------------------------------------- edge kernel
// one CTA = 256 edges, 512 threads:
// dist -> m1 = silu(HA[row]+HB[col]+dist*wr) -> m1@We2 -> silu -> red.v4 scatter
#define EPB 256
#define SM_EDGE ((128 * 128 + EPB * 132 + EPB) * 4 + EPB * 2 * 4)
__global__ void __launch_bounds__(512, 1)
k_edge(const float* __restrict__ xz, const int* __restrict__ ei,
       const float* __restrict__ We1, const float* __restrict__ We2,
       const float* __restrict__ be2, int E) {
    extern __shared__ float sm[];
    float* W2s   = sm;                       // [128][128]
    float* m1    = sm + 128 * 128;           // [EPB][132] (edge-major)
    float* distS = m1 + EPB * 132;           // [EPB]
    int*   rowS  = (int*)(distS + EPB);      // [EPB]
    int*   colS  = rowS + EPB;               // [EPB]
    int tid = threadIdx.x;
    int e0 = blockIdx.x * EPB;
    const int* rowp = ei;
    const int* colp = ei + E;

    for (int i = tid; i < 128 * 32; i += 512)
        *(float4*)(W2s + i * 4) = *(const float4*)(We2 + i * 4);

    if (tid < EPB) {
        int g = e0 + tid;
        if (g < E) {
            int r = rowp[g], c = colp[g];
            float rx = xz[3 * r], ry = xz[3 * r + 1], rz = xz[3 * r + 2];
            float cx = xz[3 * c], cy = xz[3 * c + 1], cz = xz[3 * c + 2];
            float dx = rx - cx, dy = ry - cy, dz = rz - cz;
            float u = (dx * dx + dy * dy + dz * dz) / (2.0f * rz * cz);
            distS[tid] = acoshf(1.0f + u);
            rowS[tid] = r;
            colS[tid] = c;
        } else {
            rowS[tid] = -1; colS[tid] = 0; distS[tid] = 0.0f;
        }
    }
    __syncthreads();

    // phase A: m1 tile (coalesced 512B row gathers; edge constant per warp)
    const float* wr = We1 + 256 * H;  // radial weight row of We1
    for (int i = tid; i < EPB * 32; i += 512) {
        int e = i >> 5, jv = i & 31;
        int r = rowS[e];
        float4 v = make_float4(0.f, 0.f, 0.f, 0.f);
        if (r >= 0) {
            int c = colS[e];
            float4 ha = *(const float4*)(g_HA + (size_t)r * H + jv * 4);
            float4 hb = *(const float4*)(g_HB + (size_t)c * H + jv * 4);
            float4 w  = __ldg((const float4*)(wr + jv * 4));
            float d = distS[e];
            v.x = silu_f(ha.x + hb.x + d * w.x);
            v.y = silu_f(ha.y + hb.y + d * w.y);
            v.z = silu_f(ha.z + hb.z + d * w.z);
            v.w = silu_f(ha.w + hb.w + d * w.w);
        }
        *(float4*)(m1 + e * 132 + jv * 4) = v;
    }
    __syncthreads();

    int tx = tid & 15, ty = tid >> 4;   // tx: 16 x 8 = 128 cols, ty: 32 x 8 = 256 edges
    int tx8 = tx * 8, ty8 = ty * 8;
    ull acc[8][4];
#pragma unroll
    for (int e = 0; e < 8; e++)
#pragma unroll
        for (int j = 0; j < 4; j++) acc[e][j] = 0ull;

    gemm_tile<8>(m1, 132, W2s, 128, 128, ty8, tx8, acc);

    float b2[8];
#pragma unroll
    for (int j = 0; j < 8; j++) b2[j] = __ldg(be2 + tx8 + j);

#pragma unroll
    for (int e = 0; e < 8; e++) {
        int r = rowS[ty8 + e];
        if (r < 0) continue;
        float* dstp = g_num + (size_t)r * H + tx8;
        float o[8];
#pragma unroll
        for (int jp = 0; jp < 4; jp++) upk(acc[e][jp], o[2 * jp], o[2 * jp + 1]);
#pragma unroll
        for (int j = 0; j < 8; j++) o[j] = silu_f(o[j] + b2[j]);
        red_add_v4(dstp,     o[0], o[1], o[2], o[3]);
        red_add_v4(dstp + 4, o[4], o[5], o[6], o[7]);
    }
}

// ---------------------------------------------------------------- node kernel
// out = h + silu([h | num/max(deg,1)] @ Wn1 + bn1) @ Wn2 + bn2
// 512 threads, 128 nodes/CTA, thread tile 4x8.
#define SM_NODE ((128 * 36 + 32 * 128 + 128 * 128 + 128 * 132 + 128) * 4)
__global__ void __launch_bounds__(512, 1)
k_node(const float* __restrict__ h, const float* __restrict__ Wn1,
       const float* __restrict__ bn1, const float* __restrict__ Wn2,
       const float* __restrict__ bn2, float* __restrict__ out, int n) {
    extern __shared__ float sm[];
    float* zt  = sm;                                   // [128][36] chunk of z
    float* Ws  = zt + 128 * 36;                        // [32][128] Wn1 chunk
    float* W2s = Ws + 32 * 128;                        // [128][128] Wn2
    float* t1  = W2s + 128 * 128;                      // [128][132] stage-1 act
    float* idg = t1 + 128 * 132;                       // [128] 1/max(deg,1)
    int tid = threadIdx.x;
    int n0 = blockIdx.x * 128;

    for (int i = tid; i < 128 * 32; i += 512)
        *(float4*)(W2s + i * 4) = *(const float4*)(Wn2 + i * 4);
    if (tid < 128) {
        float d = (n0 + tid < n) ? g_deg[n0 + tid] : 1.0f;
        idg[tid] = 1.0f / fmaxf(d, 1.0f);
    }
    __syncthreads();

    int tx = tid & 15, ty = tid >> 4;   // tx: 16x8 = 128 cols, ty: 32x4 = 128 rows
    int tx8 = tx * 8, ty4 = ty * 4;
    ull acc[4][4];
#pragma unroll
    for (int e = 0; e < 4; e++)
#pragma unroll
        for (int j = 0; j < 4; j++) acc[e][j] = 0ull;

    // stage 1: K = 256 in 8 chunks of 32
    for (int kc = 0; kc < 8; kc++) {
        for (int i = tid; i < 128 * 8; i += 512) {
            int nn = i >> 3, jv = i & 7;
            int nz = n0 + nn;
            float4 v = make_float4(0.f, 0.f, 0.f, 0.f);
            if (nz < n) {
                if (kc < 4) {
                    v = *(const float4*)(h + (size_t)nz * F + kc * 32 + jv * 4);
                } else {
                    v = *(const float4*)(g_num + (size_t)nz * H + (kc - 4) * 32 + jv * 4);
                    float s = idg[nn];
                    v.x *= s; v.y *= s; v.z *= s; v.w *= s;
                }
            }
            *(float4*)(zt + nn * 36 + jv * 4) = v;
        }
        for (int i = tid; i < 32 * 32; i += 512)
            *(float4*)(Ws + i * 4) =
                *(const float4*)(Wn1 + (size_t)kc * 32 * H + i * 4);
        __syncthreads();
        gemm_tile<4>(zt, 36, Ws, 128, 32, ty4, tx8, acc);
        __syncthreads();
    }

    // t1 = silu(acc + bn1)
#pragma unroll
    for (int e = 0; e < 4; e++) {
        int nn = ty4 + e;
        float o[8];
#pragma unroll
        for (int jp = 0; jp < 4; jp++) upk(acc[e][jp], o[2 * jp], o[2 * jp + 1]);
#pragma unroll
        for (int j = 0; j < 8; j++)
            t1[nn * 132 + tx8 + j] = silu_f(o[j] + __ldg(bn1 + tx8 + j));
    }
    __syncthreads();

    // stage 2: t1 @ Wn2 + residual
    ull acc2[4][4];
#pragma unroll
    for (int e = 0; e < 4; e++)
#pragma unroll
        for (int j = 0; j < 4; j++) acc2[e][j] = 0ull;

    gemm_tile<4>(t1, 132, W2s, 128, 128, ty4, tx8, acc2);

#pragma unroll
    for (int e = 0; e < 4; e++) {
        int nn = ty4 + e;
        if (n0 + nn >= n) continue;
        const float* hp = h + (size_t)(n0 + nn) * F + tx8;
        float4 h0 = *(const float4*)hp;
        float4 h1 = *(const float4*)(hp + 4);
        float o[8];
#pragma unroll
        for (int jp = 0; jp < 4; jp++) upk(acc2[e][jp], o[2 * jp], o[2 * jp + 1]);
        float4 r0 = make_float4(h0.x + o[0] + __ldg(bn2 + tx8 + 0),
                                h0.y + o[1] + __ldg(bn2 + tx8 + 1),
                                h0.z + o[2] + __ldg(bn2 + tx8 + 2),
                                h0.w + o[3] + __ldg(bn2 + tx8 + 3));
        float4 r1 = make_float4(h1.x + o[4] + __ldg(bn2 + tx8 + 4),
                                h1.y + o[5] + __ldg(bn2 + tx8 + 5),
                                h1.z + o[6] + __ldg(bn2 + tx8 + 6),
                                h1.w + o[7] + __ldg(bn2 + tx8 + 7));
        float* op = out + (size_t)(n0 + nn) * F + tx8;
        *(float4*)op       = r0;
        *(float4*)(op + 4) = r1;
    }
}

// ---------------------------------------------------------------- launch
extern "C" void kernel_launch(void* const* d_in, const int* in_sizes, int n_in,
                              void* d_out, int out_size) {
    const float* xz  = (const float*)d_in[0];
    const float* h   = (const float*)d_in[1];
    const float* We1 = (const float*)d_in[2];
    const float* be1 = (const float*)d_in[3];
    const float* We2 = (const float*)d_in[4];
    const float* be2 = (const float*)d_in[5];
    const float* Wn1 = (const float*)d_in[6];
    const float* bn1 = (const float*)d_in[7];
    const float* Wn2 = (const float*)d_in[8];
    const float* bn2 = (const float*)d_in[9];
    const int*   ei  = (const int*)d_in[10];
    float* out = (float*)d_out;

    int n = in_sizes[1] / F;
    int E = in_sizes[10] / 2;

    cudaFuncSetAttribute(k_pre,  cudaFuncAttributeMaxDynamicSharedMemorySize, SM_PRE);
    cudaFuncSetAttribute(k_edge, cudaFuncAttributeMaxDynamicSharedMemorySize, SM_EDGE);
    cudaFuncSetAttribute(k_node, cudaFuncAttributeMaxDynamicSharedMemorySize, SM_NODE);

    int nb = (n + 127) / 128;
    k_zero<<<2048, 256>>>(n);
    k_pre<<<nb, 512, SM_PRE>>>(h, We1, be1, n);
    k_deg<<<(E + 255) / 256, 256>>>(ei, E);
    k_edge<<<(E + EPB - 1) / EPB, 512, SM_EDGE>>>(xz, ei, We1, We2, be2, E);
    k_node<<<nb, 512, SM_NODE>>>(h, Wn1, bn1, Wn2, bn2, out, n);
}

// round 3
// speedup vs baseline: 1.5201x; 1.0126x over previous
#include <cuda_runtime.h>
#include <math.h>

#define N_MAX 50000
#define F 128
#define H 128

typedef unsigned long long ull;

// Scratch (device globals; no allocation allowed)
__device__ float g_HA[N_MAX * H];   // h @ We1[0:128]   + be1
__device__ float g_HB[N_MAX * H];   // h @ We1[128:256]
__device__ float g_num[N_MAX * H];  // segment sum of edge messages
__device__ float g_deg[N_MAX];      // segment counts

__device__ __forceinline__ float silu_f(float v) {
    return __fdividef(v, 1.0f + __expf(-v));
}
__device__ __forceinline__ ull pk2(float x) {
    ull r; asm("mov.b64 %0, {%1, %1};" : "=l"(r) : "f"(x)); return r;
}
__device__ __forceinline__ ull pkxy(float x, float y) {
    ull r; asm("mov.b64 %0, {%1, %2};" : "=l"(r) : "f"(x), "f"(y)); return r;
}
__device__ __forceinline__ void upk(ull v, float& x, float& y) {
    asm("mov.b64 {%0, %1}, %2;" : "=f"(x), "=f"(y) : "l"(v));
}
__device__ __forceinline__ void ffma2(ull& d, ull a, ull b) {
    asm("fma.rn.f32x2 %0, %1, %2, %0;" : "+l"(d) : "l"(a), "l"(b));
}
__device__ __forceinline__ void red_add_v4(float* p, float x, float y, float z, float w) {
    asm volatile("red.global.add.v4.f32 [%0], {%1, %2, %3, %4};"
                 :: "l"(p), "f"(x), "f"(y), "f"(z), "f"(w) : "memory");
}

// C(rows x cols) += A(rows x K, smem row-major lda) * B(K x 8cols, gmem)
// Bg is gmem pointer already offset to this thread's 8-column group; row k of
// B lives at Bg + k*128. B is CTA-invariant -> L1 broadcast hits.
template <int RPT>
__device__ __forceinline__ void gemm_g(const float* As, int lda,
                                       const float* __restrict__ Bg, int K,
                                       int row0, ull acc[][4]) {
#pragma unroll 2
    for (int k0 = 0; k0 < K; k0 += 2) {
        float2 a[RPT];
#pragma unroll
        for (int e = 0; e < RPT; e++)
            a[e] = *(const float2*)(As + (row0 + e) * lda + k0);
#pragma unroll
        for (int kk = 0; kk < 2; kk++) {
            const float4 b0 = __ldg((const float4*)(Bg + (k0 + kk) * 128));
            const float4 b1 = __ldg((const float4*)(Bg + (k0 + kk) * 128 + 4));
            ull bp0 = pkxy(b0.x, b0.y), bp1 = pkxy(b0.z, b0.w);
            ull bp2 = pkxy(b1.x, b1.y), bp3 = pkxy(b1.z, b1.w);
#pragma unroll
            for (int e = 0; e < RPT; e++) {
                ull ap = pk2(kk ? a[e].y : a[e].x);
                ffma2(acc[e][0], ap, bp0);
                ffma2(acc[e][1], ap, bp1);
                ffma2(acc[e][2], ap, bp2);
                ffma2(acc[e][3], ap, bp3);
            }
        }
    }
}

// ---------------------------------------------------------------- zero
__global__ void k_zero(int n) {
    int t4 = n * (H / 4);
    float4 z4 = make_float4(0.f, 0.f, 0.f, 0.f);
    for (int i = blockIdx.x * blockDim.x + threadIdx.x; i < t4 + n;
         i += gridDim.x * blockDim.x) {
        if (i < t4) ((float4*)g_num)[i] = z4;
        else        g_deg[i - t4] = 0.0f;
    }
}

// ---------------------------------------------------------------- precompute HA/HB
// CTA = 64 nodes x 256 output cols (HA | HB). 256 threads, 8x8 tiles.
// We1 read from gmem (L1-resident), only the h tile staged in smem.
#define SM_PRE (64 * 132 * 4)
__global__ void __launch_bounds__(256, 2)
k_pre(const float* __restrict__ h, const float* __restrict__ We1,
      const float* __restrict__ be1, int n) {
    extern __shared__ float sm[];
    float* ht = sm;  // [64][132]
    int tid = threadIdx.x;
    int n0 = blockIdx.x * 64;

    for (int i = tid; i < 64 * 32; i += 256) {
        int nn = i >> 5, jv = i & 31;
        float4 v = make_float4(0.f, 0.f, 0.f, 0.f);
        if (n0 + nn < n) v = *(const float4*)(h + (size_t)(n0 + nn) * F + jv * 4);
        *(float4*)(ht + nn * 132 + jv * 4) = v;
    }
    __syncthreads();

    int tx = tid & 31, ty = tid >> 5;   // 32 x 8 = 256 cols, 8 x 8 = 64 rows
    int tx8 = tx * 8, ty8 = ty * 8;
    bool isA = (tx8 < 128);
    const float* Bg = isA ? (We1 + tx8)
                          : (We1 + (size_t)128 * 128 + (tx8 - 128));
    ull acc[8][4];
#pragma unroll
    for (int e = 0; e < 8; e++)
#pragma unroll
        for (int j = 0; j < 4; j++) acc[e][j] = 0ull;

    gemm_g<8>(ht, 132, Bg, 128, ty8, acc);

    float* dstb = isA ? g_HA : g_HB;
    int cb = isA ? tx8 : (tx8 - 128);
    float bias[8];
#pragma unroll
    for (int j = 0; j < 8; j++) bias[j] = isA ? __ldg(be1 + cb + j) : 0.0f;

#pragma unroll
    for (int e = 0; e < 8; e++) {
        int nn = ty8 + e;
        if (n0 + nn >= n) continue;
        float o[8];
#pragma unroll
        for (int jp = 0; jp < 4; jp++) upk(acc[e][jp], o[2 * jp], o[2 * jp + 1]);
#pragma unroll
        for (int j = 0; j < 8; j++) o[j] += bias[j];
        float* p = dstb + (size_t)(n0 + nn) * H + cb;
        *(float4*)p       = make_float4(o[0], o[1], o[2], o[3]);
        *(float4*)(p + 4) = make_float4(o[4], o[5], o[6], o[7]);
    }
}

// ---------------------------------------------------------------- edge kernel
// CTA = 128 edges, 256 threads, 2 CTAs/SM. We2 read from gmem (L1-hot).
// dist(+deg) -> m1 = silu(HA[row]+HB[col]+dist*wr) -> m1@We2 -> silu -> red.v4
#define EPB 128
#define SM_EDGE ((EPB * 132 + EPB) * 4 + EPB * 2 * 4)
__global__ void __launch_bounds__(256, 2)
k_edge(const float* __restrict__ xz, const int* __restrict__ ei,
       const float* __restrict__ We1, const float* __restrict__ We2,
       const float* __restrict__ be2, int E) {
    extern __shared__ float sm[];
    float* m1    = sm;                       // [EPB][132] (edge-major)
    float* distS = m1 + EPB * 132;           // [EPB]
    int*   rowS  = (int*)(distS + EPB);      // [EPB]
    int*   colS  = rowS + EPB;               // [EPB]
    int tid = threadIdx.x;
    int e0 = blockIdx.x * EPB;
    const int* rowp = ei;
    const int* colp = ei + E;

    if (tid < EPB) {
        int g = e0 + tid;
        if (g < E) {
            int r = rowp[g], c = colp[g];
            float rx = xz[3 * r], ry = xz[3 * r + 1], rz = xz[3 * r + 2];
            float cx = xz[3 * c], cy = xz[3 * c + 1], cz = xz[3 * c + 2];
            float dx = rx - cx, dy = ry - cy, dz = rz - cz;
            float u = (dx * dx + dy * dy + dz * dz) / (2.0f * rz * cz);
            distS[tid] = acoshf(1.0f + u);
            rowS[tid] = r;
            colS[tid] = c;
            atomicAdd(&g_deg[r], 1.0f);  // degree folded in
        } else {
            rowS[tid] = -1; colS[tid] = 0; distS[tid] = 0.0f;
        }
    }
    __syncthreads();

    // phase A: m1 tile (coalesced 512B row gathers; edge constant per warp)
    const float* wr = We1 + 256 * H;  // radial weight row of We1
    for (int i = tid; i < EPB * 32; i += 256) {
        int e = i >> 5, jv = i & 31;
        int r = rowS[e];
        float4 v = make_float4(0.f, 0.f, 0.f, 0.f);
        if (r >= 0) {
            int c = colS[e];
            float4 ha = *(const float4*)(g_HA + (size_t)r * H + jv * 4);
            float4 hb = *(const float4*)(g_HB + (size_t)c * H + jv * 4);
            float4 w  = __ldg((const float4*)(wr + jv * 4));
            float d = distS[e];
            v.x = silu_f(ha.x + hb.x + d * w.x);
            v.y = silu_f(ha.y + hb.y + d * w.y);
            v.z = silu_f(ha.z + hb.z + d * w.z);
            v.w = silu_f(ha.w + hb.w + d * w.w);
        }
        *(float4*)(m1 + e * 132 + jv * 4) = v;
    }
    __syncthreads();

    int tx = tid & 15, ty = tid >> 4;   // 16 x 8 = 128 cols, 16 x 8 = 128 edges
    int tx8 = tx * 8, ty8 = ty * 8;
    ull acc[8][4];
#pragma unroll
    for (int e = 0; e < 8; e++)
#pragma unroll
        for (int j = 0; j < 4; j++) acc[e][j] = 0ull;

    gemm_g<8>(m1, 132, We2 + tx8, 128, ty8, acc);

    float b2[8];
#pragma unroll
    for (int j = 0; j < 8; j++) b2[j] = __ldg(be2 + tx8 + j);

#pragma unroll
    for (int e = 0; e < 8; e++) {
        int r = rowS[ty8 + e];
        if (r < 0) continue;
        float* dstp = g_num + (size_t)r * H + tx8;
        float o[8];
#pragma unroll
        for (int jp = 0; jp < 4; jp++) upk(acc[e][jp], o[2 * jp], o[2 * jp + 1]);
#pragma unroll
        for (int j = 0; j < 8; j++) o[j] = silu_f(o[j] + b2[j]);
        red_add_v4(dstp,     o[0], o[1], o[2], o[3]);
        red_add_v4(dstp + 4, o[4], o[5], o[6], o[7]);
    }
}

// ---------------------------------------------------------------- node kernel
// out = h + silu([h | num/max(deg,1)] @ Wn1 + bn1) @ Wn2 + bn2
// CTA = 128 nodes, 256 threads, 8x8 tiles, weights from gmem, 2 CTAs/SM.
#define SM_NODE ((128 * 36 + 128 * 132 + 128) * 4)
__global__ void __launch_bounds__(256, 2)
k_node(const float* __restrict__ h, const float* __restrict__ Wn1,
       const float* __restrict__ bn1, const float* __restrict__ Wn2,
       const float* __restrict__ bn2, float* __restrict__ out, int n) {
    extern __shared__ float sm[];
    float* zt  = sm;                 // [128][36] chunk of z (32 k + pad)
    float* t1  = zt + 128 * 36;      // [128][132] stage-1 act
    float* idg = t1 + 128 * 132;     // [128] 1/max(deg,1)
    int tid = threadIdx.x;
    int n0 = blockIdx.x * 128;

    if (tid < 128) {
        float d = (n0 + tid < n) ? g_deg[n0 + tid] : 1.0f;
        idg[tid] = 1.0f / fmaxf(d, 1.0f);
    }
    __syncthreads();

    int tx = tid & 15, ty = tid >> 4;   // 16 x 8 = 128 cols, 16 x 8 = 128 rows
    int tx8 = tx * 8, ty8 = ty * 8;
    ull acc[8][4];
#pragma unroll
    for (int e = 0; e < 8; e++)
#pragma unroll
        for (int j = 0; j < 4; j++) acc[e][j] = 0ull;

    // stage 1: K = 256 in 8 chunks of 32 (z staged, Wn1 from gmem)
    for (int kc = 0; kc < 8; kc++) {
        for (int i = tid; i < 128 * 8; i += 256) {
            int nn = i >> 3, jv = i & 7;
            int nz = n0 + nn;
            float4 v = make_float4(0.f, 0.f, 0.f, 0.f);
            if (nz < n) {
                if (kc < 4) {
                    v = *(const float4*)(h + (size_t)nz * F + kc * 32 + jv * 4);
                } else {
                    v = *(const float4*)(g_num + (size_t)nz * H + (kc - 4) * 32 + jv * 4);
                    float s = idg[nn];
                    v.x *= s; v.y *= s; v.z *= s; v.w *= s;
                }
            }
            *(float4*)(zt + nn * 36 + jv * 4) = v;
        }
        __syncthreads();
        gemm_g<8>(zt, 36, Wn1 + (size_t)kc * 32 * H + tx8, 32, ty8, acc);
        __syncthreads();
    }

    // t1 = silu(acc + bn1)
#pragma unroll
    for (int e = 0; e < 8; e++) {
        int nn = ty8 + e;
        float o[8];
#pragma unroll
        for (int jp = 0; jp < 4; jp++) upk(acc[e][jp], o[2 * jp], o[2 * jp + 1]);
#pragma unroll
        for (int j = 0; j < 8; j++)
            t1[nn * 132 + tx8 + j] = silu_f(o[j] + __ldg(bn1 + tx8 + j));
    }
    __syncthreads();

    // stage 2: t1 @ Wn2 + residual
    ull acc2[8][4];
#pragma unroll
    for (int e = 0; e < 8; e++)
#pragma unroll
        for (int j = 0; j < 4; j++) acc2[e][j] = 0ull;

    gemm_g<8>(t1, 132, Wn2 + tx8, 128, ty8, acc2);

#pragma unroll
    for (int e = 0; e < 8; e++) {
        int nn = ty8 + e;
        if (n0 + nn >= n) continue;
        const float* hp = h + (size_t)(n0 + nn) * F + tx8;
        float4 h0 = *(const float4*)hp;
        float4 h1 = *(const float4*)(hp + 4);
        float o[8];
#pragma unroll
        for (int jp = 0; jp < 4; jp++) upk(acc2[e][jp], o[2 * jp], o[2 * jp + 1]);
        float4 r0 = make_float4(h0.x + o[0] + __ldg(bn2 + tx8 + 0),
                                h0.y + o[1] + __ldg(bn2 + tx8 + 1),
                                h0.z + o[2] + __ldg(bn2 + tx8 + 2),
                                h0.w + o[3] + __ldg(bn2 + tx8 + 3));
        float4 r1 = make_float4(h1.x + o[4] + __ldg(bn2 + tx8 + 4),
                                h1.y + o[5] + __ldg(bn2 + tx8 + 5),
                                h1.z + o[6] + __ldg(bn2 + tx8 + 6),
                                h1.w + o[7] + __ldg(bn2 + tx8 + 7));
        float* op = out + (size_t)(n0 + nn) * F + tx8;
        *(float4*)op       = r0;
        *(float4*)(op + 4) = r1;
    }
}

// ---------------------------------------------------------------- launch
extern "C" void kernel_launch(void* const* d_in, const int* in_sizes, int n_in,
                              void* d_out, int out_size) {
    const float* xz  = (const float*)d_in[0];
    const float* h   = (const float*)d_in[1];
    const float* We1 = (const float*)d_in[2];
    const float* be1 = (const float*)d_in[3];
    const float* We2 = (const float*)d_in[4];
    const float* be2 = (const float*)d_in[5];
    const float* Wn1 = (const float*)d_in[6];
    const float* bn1 = (const float*)d_in[7];
    const float* Wn2 = (const float*)d_in[8];
    const float* bn2 = (const float*)d_in[9];
    const int*   ei  = (const int*)d_in[10];
    float* out = (float*)d_out;

    int n = in_sizes[1] / F;
    int E = in_sizes[10] / 2;

    cudaFuncSetAttribute(k_pre,  cudaFuncAttributeMaxDynamicSharedMemorySize, SM_PRE);
    cudaFuncSetAttribute(k_edge, cudaFuncAttributeMaxDynamicSharedMemorySize, SM_EDGE);
    cudaFuncSetAttribute(k_node, cudaFuncAttributeMaxDynamicSharedMemorySize, SM_NODE);

    k_zero<<<2048, 256>>>(n);
    k_pre<<<(n + 63) / 64, 256, SM_PRE>>>(h, We1, be1, n);
    k_edge<<<(E + EPB - 1) / EPB, 256, SM_EDGE>>>(xz, ei, We1, We2, be2, E);
    k_node<<<(n + 127) / 128, 256, SM_NODE>>>(h, Wn1, bn1, Wn2, bn2, out, n);
}

// round 5
// speedup vs baseline: 1.5936x; 1.0483x over previous
#include <cuda_runtime.h>
#include <cuda_fp16.h>
#include <math.h>
#include <cstdint>

#define N_MAX 50000
#define F 128
#define H 128

typedef unsigned long long ull;

// Scratch (device globals; no allocation allowed)
__device__ float g_HA[N_MAX * H];   // h @ We1[0:128]   + be1
__device__ float g_HB[N_MAX * H];   // h @ We1[128:256]
__device__ float g_num[N_MAX * H];  // segment sum of edge messages
__device__ float g_deg[N_MAX];      // segment counts
__device__ __half g_W2hi[H * H];    // We2^T hi  [n][k]
__device__ __half g_W2lo[H * H];    // We2^T lo  [n][k]

__device__ __forceinline__ float silu_f(float v) {
    return __fdividef(v, 1.0f + __expf(-v));
}
__device__ __forceinline__ ull pk2(float x) {
    ull r; asm("mov.b64 %0, {%1, %1};" : "=l"(r) : "f"(x)); return r;
}
__device__ __forceinline__ ull pkxy(float x, float y) {
    ull r; asm("mov.b64 %0, {%1, %2};" : "=l"(r) : "f"(x), "f"(y)); return r;
}
__device__ __forceinline__ void upk(ull v, float& x, float& y) {
    asm("mov.b64 {%0, %1}, %2;" : "=f"(x), "=f"(y) : "l"(v));
}
__device__ __forceinline__ void ffma2(ull& d, ull a, ull b) {
    asm("fma.rn.f32x2 %0, %1, %2, %0;" : "+l"(d) : "l"(a), "l"(b));
}
__device__ __forceinline__ void red_add_v4(float* p, float x, float y, float z, float w) {
    asm volatile("red.global.add.v4.f32 [%0], {%1, %2, %3, %4};"
                 :: "l"(p), "f"(x), "f"(y), "f"(z), "f"(w) : "memory");
}
__device__ __forceinline__ uint32_t smem_u32(const void* p) {
    uint32_t a;
    asm("{ .reg .u64 t; cvta.to.shared.u64 t, %1; cvt.u32.u64 %0, t; }"
        : "=r"(a) : "l"(p));
    return a;
}
__device__ __forceinline__ uint32_t pkh(__half a, __half b) {
    __half2 h2 = __halves2half2(a, b);
    return *(uint32_t*)&h2;
}
__device__ __forceinline__ void ldsm4(uint32_t* r, uint32_t addr) {
    asm volatile("ldmatrix.sync.aligned.m8n8.x4.shared.b16 {%0,%1,%2,%3}, [%4];"
                 : "=r"(r[0]), "=r"(r[1]), "=r"(r[2]), "=r"(r[3]) : "r"(addr));
}
__device__ __forceinline__ void mma16816(float* d, const uint32_t* a,
                                         const uint32_t* b) {
    asm volatile(
        "mma.sync.aligned.m16n8k16.row.col.f32.f16.f16.f32 "
        "{%0,%1,%2,%3}, {%4,%5,%6,%7}, {%8,%9}, {%0,%1,%2,%3};"
        : "+f"(d[0]), "+f"(d[1]), "+f"(d[2]), "+f"(d[3])
        : "r"(a[0]), "r"(a[1]), "r"(a[2]), "r"(a[3]), "r"(b[0]), "r"(b[1]));
}

// ---------------------------------------------------------------- zero
__global__ void k_zero(int n) {
    int t4 = n * (H / 4);
    float4 z4 = make_float4(0.f, 0.f, 0.f, 0.f);
    for (int i = blockIdx.x * blockDim.x + threadIdx.x; i < t4 + n;
         i += gridDim.x * blockDim.x) {
        if (i < t4) ((float4*)g_num)[i] = z4;
        else        g_deg[i - t4] = 0.0f;
    }
}

// ---------------------------------------------------------------- We2^T f16 split
__global__ void k_wsplit(const float* __restrict__ We2) {
    int i = blockIdx.x * blockDim.x + threadIdx.x;
    if (i < H * H) {
        int k = i >> 7, n = i & 127;
        float v = We2[i];  // We2[k][n]
        __half hi = __float2half_rn(v);
        __half lo = __float2half_rn(v - __half2float(hi));
        g_W2hi[n * H + k] = hi;
        g_W2lo[n * H + k] = lo;
    }
}

// ===================== SIMT helper GEMM (pre/node kernels) ================
template <int RPT>
__device__ __forceinline__ void gemm_g(const float* As, int lda,
                                       const float* __restrict__ Bg, int K,
                                       int row0, ull acc[][4]) {
#pragma unroll 2
    for (int k0 = 0; k0 < K; k0 += 2) {
        float2 a[RPT];
#pragma unroll
        for (int e = 0; e < RPT; e++)
            a[e] = *(const float2*)(As + (row0 + e) * lda + k0);
#pragma unroll
        for (int kk = 0; kk < 2; kk++) {
            const float4 b0 = __ldg((const float4*)(Bg + (k0 + kk) * 128));
            const float4 b1 = __ldg((const float4*)(Bg + (k0 + kk) * 128 + 4));
            ull bp0 = pkxy(b0.x, b0.y), bp1 = pkxy(b0.z, b0.w);
            ull bp2 = pkxy(b1.x, b1.y), bp3 = pkxy(b1.z, b1.w);
#pragma unroll
            for (int e = 0; e < RPT; e++) {
                ull ap = pk2(kk ? a[e].y : a[e].x);
                ffma2(acc[e][0], ap, bp0);
                ffma2(acc[e][1], ap, bp1);
                ffma2(acc[e][2], ap, bp2);
                ffma2(acc[e][3], ap, bp3);
            }
        }
    }
}

// ---------------------------------------------------------------- precompute HA/HB
#define SM_PRE (64 * 132 * 4)
__global__ void __launch_bounds__(256, 2)
k_pre(const float* __restrict__ h, const float* __restrict__ We1,
      const float* __restrict__ be1, int n) {
    extern __shared__ float sm[];
    float* ht = sm;  // [64][132]
    int tid = threadIdx.x;
    int n0 = blockIdx.x * 64;

    for (int i = tid; i < 64 * 32; i += 256) {
        int nn = i >> 5, jv = i & 31;
        float4 v = make_float4(0.f, 0.f, 0.f, 0.f);
        if (n0 + nn < n) v = *(const float4*)(h + (size_t)(n0 + nn) * F + jv * 4);
        *(float4*)(ht + nn * 132 + jv * 4) = v;
    }
    __syncthreads();

    int tx = tid & 31, ty = tid >> 5;
    int tx8 = tx * 8, ty8 = ty * 8;
    bool isA = (tx8 < 128);
    const float* Bg = isA ? (We1 + tx8) : (We1 + (size_t)128 * 128 + (tx8 - 128));
    ull acc[8][4];
#pragma unroll
    for (int e = 0; e < 8; e++)
#pragma unroll
        for (int j = 0; j < 4; j++) acc[e][j] = 0ull;

    gemm_g<8>(ht, 132, Bg, 128, ty8, acc);

    float* dstb = isA ? g_HA : g_HB;
    int cb = isA ? tx8 : (tx8 - 128);
    float bias[8];
#pragma unroll
    for (int j = 0; j < 8; j++) bias[j] = isA ? __ldg(be1 + cb + j) : 0.0f;

#pragma unroll
    for (int e = 0; e < 8; e++) {
        int nn = ty8 + e;
        if (n0 + nn >= n) continue;
        float o[8];
#pragma unroll
        for (int jp = 0; jp < 4; jp++) upk(acc[e][jp], o[2 * jp], o[2 * jp + 1]);
#pragma unroll
        for (int j = 0; j < 8; j++) o[j] += bias[j];
        float* p = dstb + (size_t)(n0 + nn) * H + cb;
        *(float4*)p       = make_float4(o[0], o[1], o[2], o[3]);
        *(float4*)(p + 4) = make_float4(o[4], o[5], o[6], o[7]);
    }
}

// ==================== edge kernel: persistent mma.sync ====================
// Tile = 256 edges, 512 threads (16 warps), 1 CTA/SM.
// SMEM: A_hi/A_lo f16 [256][136], B_hi/B_lo f16 [128][136] (We2^T, staged once),
// rowS[256]. C (f32 [256][132]) reuses the A region after the MMA barrier.
// Per tile: gather+silu+f16 split -> ldmatrix+mma (3 passes) -> silu+bias -> C
// -> coalesced red.global.add.v4 scatter.
#define TILE 256
#define OFF_ALO (TILE * 136 * 2)              // 69632
#define OFF_BHI (OFF_ALO + TILE * 136 * 2)    // 139264
#define OFF_BLO (OFF_BHI + 128 * 136 * 2)     // 174080
#define OFF_ROW (OFF_BLO + 128 * 136 * 2)     // 208896
#define SM_EDGE (OFF_ROW + TILE * 4)          // 209920

__global__ void __launch_bounds__(512, 1)
k_edge(const float* __restrict__ xz, const int* __restrict__ ei,
       const float* __restrict__ We1, const float* __restrict__ be2,
       int E, int ntiles) {
    extern __shared__ char smc[];
    uint32_t smb = smem_u32(smc);
    int tid = threadIdx.x;
    int lane = tid & 31, warp = tid >> 5;
    int m0 = warp * 16;

    // Stage B hi/lo once: [128][136] f16, row n, k contiguous
    for (int i = tid; i < 128 * 64; i += 512) {
        int n = i >> 6, j = i & 63;
        *(uint32_t*)(smc + OFF_BHI + n * 272 + j * 4) = ((const uint32_t*)g_W2hi)[i];
        *(uint32_t*)(smc + OFF_BLO + n * 272 + j * 4) = ((const uint32_t*)g_W2lo)[i];
    }

    const float* wr = We1 + 256 * H;  // radial weight row
    const int* rowp = ei;
    const int* colp = ei + E;

    // ldmatrix lane addresses
    uint32_t aHi = smb + (uint32_t)(m0 + (lane & 15)) * 272 + ((lane >> 4) * 8) * 2;
    uint32_t aLo = aHi + OFF_ALO;
    uint32_t bOff = (uint32_t)(((lane >> 4) & 1) * 8 + (lane & 7)) * 272 +
                    (uint32_t)(((lane >> 3) & 1) * 8) * 2;
    uint32_t bHi = smb + OFF_BHI + bOff;
    uint32_t bLo = smb + OFF_BLO + bOff;

    float* Cs = (float*)smc;                // [256][132] f32, reuses A region
    int* rowS = (int*)(smc + OFF_ROW);

    int erow = tid >> 1;
    int halfk = tid & 1;
    int kb = halfk * 64;
    uint32_t dstHi = smb + (uint32_t)erow * 272 + (uint32_t)kb * 2;
    uint32_t dstLo = dstHi + OFF_ALO;

    for (int t = blockIdx.x; t < ntiles; t += gridDim.x) {
        __syncthreads();  // A/C reuse guard (also orders B staging on iter 1)

        // ---- gather + dist + silu + f16 split -> smem A ----
        int e = t * TILE + erow;
        int r = -1, c = 0;
        float dist = 0.0f;
        if (e < E) {
            r = rowp[e]; c = colp[e];
            float rx = xz[3 * r], ry = xz[3 * r + 1], rz = xz[3 * r + 2];
            float cx = xz[3 * c], cy = xz[3 * c + 1], cz = xz[3 * c + 2];
            float dx = rx - cx, dy = ry - cy, dz = rz - cz;
            float u = (dx * dx + dy * dy + dz * dz) / (2.0f * rz * cz);
            dist = acoshf(1.0f + u);
            if (halfk == 0) {
                rowS[erow] = r;
                atomicAdd(&g_deg[r], 1.0f);
            }
        } else if (halfk == 0) {
            rowS[erow] = -1;
        }

        const float4* pa = (const float4*)(g_HA + (size_t)(r < 0 ? 0 : r) * H + kb);
        const float4* pb = (const float4*)(g_HB + (size_t)(r < 0 ? 0 : c) * H + kb);
        const float4* pw = (const float4*)(wr + kb);
#pragma unroll
        for (int jj = 0; jj < 8; jj++) {
            float v[8];
            if (r >= 0) {
#pragma unroll
                for (int q = 0; q < 2; q++) {
                    float4 A4 = pa[jj * 2 + q], B4 = pb[jj * 2 + q];
                    float4 W4 = __ldg(pw + jj * 2 + q);
                    v[4 * q + 0] = silu_f(A4.x + B4.x + dist * W4.x);
                    v[4 * q + 1] = silu_f(A4.y + B4.y + dist * W4.y);
                    v[4 * q + 2] = silu_f(A4.z + B4.z + dist * W4.z);
                    v[4 * q + 3] = silu_f(A4.w + B4.w + dist * W4.w);
                }
            } else {
#pragma unroll
                for (int q = 0; q < 8; q++) v[q] = 0.0f;
            }
            uint32_t hw[4], lw[4];
#pragma unroll
            for (int p = 0; p < 4; p++) {
                float x = v[2 * p], y = v[2 * p + 1];
                __half hx = __float2half_rn(x), hy = __float2half_rn(y);
                __half lx = __float2half_rn(x - __half2float(hx));
                __half ly = __float2half_rn(y - __half2float(hy));
                hw[p] = pkh(hx, hy);
                lw[p] = pkh(lx, ly);
            }
            *(uint4*)(smc + (dstHi - smb) + jj * 16) =
                make_uint4(hw[0], hw[1], hw[2], hw[3]);
            *(uint4*)(smc + (dstLo - smb) + jj * 16) =
                make_uint4(lw[0], lw[1], lw[2], lw[3]);
        }
        __syncthreads();

        // ---- MMA: warp computes rows m0..m0+15 x all 128 cols ----
        float acc[16][4];
#pragma unroll
        for (int nt = 0; nt < 16; nt++)
#pragma unroll
            for (int q = 0; q < 4; q++) acc[nt][q] = 0.0f;

#pragma unroll
        for (int k = 0; k < 8; k++) {
            uint32_t ah[4], al[4];
            ldsm4(ah, aHi + k * 32);
            ldsm4(al, aLo + k * 32);
#pragma unroll
            for (int j = 0; j < 8; j++) {
                uint32_t bh[4], bl[4];
                ldsm4(bh, bHi + (uint32_t)j * 16 * 272 + k * 32);
                ldsm4(bl, bLo + (uint32_t)j * 16 * 272 + k * 32);
                mma16816(acc[2 * j], ah, bh);
                mma16816(acc[2 * j], al, bh);
                mma16816(acc[2 * j], ah, bl);
                mma16816(acc[2 * j + 1], ah, bh + 2);
                mma16816(acc[2 * j + 1], al, bh + 2);
                mma16816(acc[2 * j + 1], ah, bl + 2);
            }
        }
        __syncthreads();  // everyone done reading A before C overwrite

        // ---- silu + bias -> C (smem) ----
        int g = lane >> 2, tq = lane & 3;
#pragma unroll
        for (int nt = 0; nt < 16; nt++) {
            int col = nt * 8 + tq * 2;
            float b0 = __ldg(be2 + col), b1 = __ldg(be2 + col + 1);
            float v0 = silu_f(acc[nt][0] + b0), v1 = silu_f(acc[nt][1] + b1);
            float v2 = silu_f(acc[nt][2] + b0), v3 = silu_f(acc[nt][3] + b1);
            *(float2*)(Cs + (m0 + g) * 132 + col) = make_float2(v0, v1);
            *(float2*)(Cs + (m0 + g + 8) * 132 + col) = make_float2(v2, v3);
        }
        __syncthreads();

        // ---- coalesced scatter ----
        for (int i = tid; i < TILE * 32; i += 512) {
            int ee = i >> 5, grp = i & 31;
            int rr = rowS[ee];
            if (rr >= 0) {
                const float* cp = Cs + ee * 132 + grp * 4;
                red_add_v4(g_num + (size_t)rr * H + grp * 4,
                           cp[0], cp[1], cp[2], cp[3]);
            }
        }
    }
}

// ---------------------------------------------------------------- node kernel
#define SM_NODE ((128 * 36 + 128 * 132 + 128) * 4)
__global__ void __launch_bounds__(256, 2)
k_node(const float* __restrict__ h, const float* __restrict__ Wn1,
       const float* __restrict__ bn1, const float* __restrict__ Wn2,
       const float* __restrict__ bn2, float* __restrict__ out, int n) {
    extern __shared__ float sm[];
    float* zt  = sm;                 // [128][36]
    float* t1  = zt + 128 * 36;      // [128][132]
    float* idg = t1 + 128 * 132;     // [128]
    int tid = threadIdx.x;
    int n0 = blockIdx.x * 128;

    if (tid < 128) {
        float d = (n0 + tid < n) ? g_deg[n0 + tid] : 1.0f;
        idg[tid] = 1.0f / fmaxf(d, 1.0f);
    }
    __syncthreads();

    int tx = tid & 15, ty = tid >> 4;
    int tx8 = tx * 8, ty8 = ty * 8;
    ull acc[8][4];
#pragma unroll
    for (int e = 0; e < 8; e++)
#pragma unroll
        for (int j = 0; j < 4; j++) acc[e][j] = 0ull;

    for (int kc = 0; kc < 8; kc++) {
        for (int i = tid; i < 128 * 8; i += 256) {
            int nn = i >> 3, jv = i & 7;
            int nz = n0 + nn;
            float4 v = make_float4(0.f, 0.f, 0.f, 0.f);
            if (nz < n) {
                if (kc < 4) {
                    v = *(const float4*)(h + (size_t)nz * F + kc * 32 + jv * 4);
                } else {
                    v = *(const float4*)(g_num + (size_t)nz * H + (kc - 4) * 32 + jv * 4);
                    float s = idg[nn];
                    v.x *= s; v.y *= s; v.z *= s; v.w *= s;
                }
            }
            *(float4*)(zt + nn * 36 + jv * 4) = v;
        }
        __syncthreads();
        gemm_g<8>(zt, 36, Wn1 + (size_t)kc * 32 * H + tx8, 32, ty8, acc);
        __syncthreads();
    }

#pragma unroll
    for (int e = 0; e < 8; e++) {
        int nn = ty8 + e;
        float o[8];
#pragma unroll
        for (int jp = 0; jp < 4; jp++) upk(acc[e][jp], o[2 * jp], o[2 * jp + 1]);
#pragma unroll
        for (int j = 0; j < 8; j++)
            t1[nn * 132 + tx8 + j] = silu_f(o[j] + __ldg(bn1 + tx8 + j));
    }
    __syncthreads();

    ull acc2[8][4];
#pragma unroll
    for (int e = 0; e < 8; e++)
#pragma unroll
        for (int j = 0; j < 4; j++) acc2[e][j] = 0ull;

    gemm_g<8>(t1, 132, Wn2 + tx8, 128, ty8, acc2);

#pragma unroll
    for (int e = 0; e < 8; e++) {
        int nn = ty8 + e;
        if (n0 + nn >= n) continue;
        const float* hp = h + (size_t)(n0 + nn) * F + tx8;
        float4 h0 = *(const float4*)hp;
        float4 h1 = *(const float4*)(hp + 4);
        float o[8];
#pragma unroll
        for (int jp = 0; jp < 4; jp++) upk(acc2[e][jp], o[2 * jp], o[2 * jp + 1]);
        float4 r0 = make_float4(h0.x + o[0] + __ldg(bn2 + tx8 + 0),
                                h0.y + o[1] + __ldg(bn2 + tx8 + 1),
                                h0.z + o[2] + __ldg(bn2 + tx8 + 2),
                                h0.w + o[3] + __ldg(bn2 + tx8 + 3));
        float4 r1 = make_float4(h1.x + o[4] + __ldg(bn2 + tx8 + 4),
                                h1.y + o[5] + __ldg(bn2 + tx8 + 5),
                                h1.z + o[6] + __ldg(bn2 + tx8 + 6),
                                h1.w + o[7] + __ldg(bn2 + tx8 + 7));
        float* op = out + (size_t)(n0 + nn) * F + tx8;
        *(float4*)op       = r0;
        *(float4*)(op + 4) = r1;
    }
}

// ---------------------------------------------------------------- launch
extern "C" void kernel_launch(void* const* d_in, const int* in_sizes, int n_in,
                              void* d_out, int out_size) {
    const float* xz  = (const float*)d_in[0];
    const float* h   = (const float*)d_in[1];
    const float* We1 = (const float*)d_in[2];
    const float* be1 = (const float*)d_in[3];
    const float* We2 = (const float*)d_in[4];
    const float* be2 = (const float*)d_in[5];
    const float* Wn1 = (const float*)d_in[6];
    const float* bn1 = (const float*)d_in[7];
    const float* Wn2 = (const float*)d_in[8];
    const float* bn2 = (const float*)d_in[9];
    const int*   ei  = (const int*)d_in[10];
    float* out = (float*)d_out;

    int n = in_sizes[1] / F;
    int E = in_sizes[10] / 2;
    int ntiles = (E + TILE - 1) / TILE;

    cudaFuncSetAttribute(k_pre,  cudaFuncAttributeMaxDynamicSharedMemorySize, SM_PRE);
    cudaFuncSetAttribute(k_edge, cudaFuncAttributeMaxDynamicSharedMemorySize, SM_EDGE);
    cudaFuncSetAttribute(k_node, cudaFuncAttributeMaxDynamicSharedMemorySize, SM_NODE);

    k_zero<<<2048, 256>>>(n);
    k_wsplit<<<(H * H + 255) / 256, 256>>>(We2);
    k_pre<<<(n + 63) / 64, 256, SM_PRE>>>(h, We1, be1, n);
    k_edge<<<148, 512, SM_EDGE>>>(xz, ei, We1, be2, E, ntiles);
    k_node<<<(n + 127) / 128, 256, SM_NODE>>>(h, Wn1, bn1, Wn2, bn2, out, n);
}